// round 5
// baseline (speedup 1.0000x reference)
#include <cuda_runtime.h>
#include <math.h>

typedef unsigned long long u64;

#define TOKENS 1024
#define CDIM   512
#define QKVD   1536
#define NSEQ   256
#define HEADS  8
#define DH     64
#define QT     32
#define KT     64
#define EPSF   1e-6f
#define T_SMALL 0.009f
#define CH     132            // q-side chunk stride: 32*4 + 4 pad floats

// ---------------- packed f32x2 helpers ----------------
__device__ __forceinline__ u64 pk2(float lo, float hi) {
    u64 r; asm("mov.b64 %0,{%1,%2};" : "=l"(r) : "f"(lo), "f"(hi)); return r;
}
__device__ __forceinline__ void up2(u64 v, float& lo, float& hi) {
    asm("mov.b64 {%0,%1},%2;" : "=f"(lo), "=f"(hi) : "l"(v));
}
__device__ __forceinline__ u64 fadd2(u64 a, u64 b) {
    u64 r; asm("add.rn.f32x2 %0,%1,%2;" : "=l"(r) : "l"(a), "l"(b)); return r;
}
__device__ __forceinline__ u64 fmul2(u64 a, u64 b) {
    u64 r; asm("mul.rn.f32x2 %0,%1,%2;" : "=l"(r) : "l"(a), "l"(b)); return r;
}
__device__ __forceinline__ u64 ffma2(u64 a, u64 b, u64 c) {
    u64 r; asm("fma.rn.f32x2 %0,%1,%2,%3;" : "=l"(r) : "l"(a), "l"(b), "l"(c)); return r;
}

// ---------------- device scratch ----------------
__device__ float g_qkv[TOKENS * QKVD];
__device__ float g_att[TOKENS * CDIM];
__device__ float g_qs [TOKENS * CDIM];
__device__ float g_qc [TOKENS * CDIM];
__device__ float g_knv[TOKENS * CDIM];   // -k
__device__ float g_kns[TOKENS * CDIM];   // -sin(R k)
__device__ float g_kc [TOKENS * CDIM];   //  cos(R k)

// ---------------------------------------------------------------------------
// FFMA2 GEMM: C[M,Ncols] = A[M,K]*Bw[Ncols,K]^T (+bias).
// 64x64 tile, BK=16, 256 threads, per-thread 4Mx4N (2 f32x2 M-pairs).
// A pairs adjacent in As rows -> 1 LDS.128 (warp-broadcast).
// B stored duplicated {b,b} float2 -> 2 LDS.128 give 4 packed operands, no MOVs.
// If TRIG: epilogue computes sin/cos tables for the q/k column regions.
// ---------------------------------------------------------------------------
template<bool TRIG>
__global__ __launch_bounds__(256)
void gemm2f(const float* __restrict__ A, const float* __restrict__ Bw,
            const float* __restrict__ bias, float* __restrict__ C,
            int Ncols, int K,
            const float* __restrict__ paramR,
            float* __restrict__ gqs, float* __restrict__ gqc,
            float* __restrict__ gknv, float* __restrict__ gkns,
            float* __restrict__ gkc)
{
    __shared__ __align__(16) float  As[16][68];
    __shared__ __align__(16) float2 Bs[16][66];
    const int t  = threadIdx.x;
    const int m0 = blockIdx.y * 64;
    const int n0 = blockIdx.x * 64;
    const int tx = t & 15, ty = t >> 4;

    u64 acc[2][4];
    #pragma unroll
    for (int p = 0; p < 2; p++)
        #pragma unroll
        for (int n = 0; n < 4; n++) acc[p][n] = 0ull;

    const int am = t >> 2, akq = (t & 3) << 2;

    float4 pa = *(const float4*)&A [(m0 + am) * K + akq];
    float4 pb = *(const float4*)&Bw[(n0 + am) * K + akq];

    const int nit = K / 16;
    for (int it = 0; it < nit; ++it) {
        As[akq + 0][am] = pa.x; As[akq + 1][am] = pa.y;
        As[akq + 2][am] = pa.z; As[akq + 3][am] = pa.w;
        Bs[akq + 0][am] = make_float2(pb.x, pb.x);
        Bs[akq + 1][am] = make_float2(pb.y, pb.y);
        Bs[akq + 2][am] = make_float2(pb.z, pb.z);
        Bs[akq + 3][am] = make_float2(pb.w, pb.w);
        __syncthreads();
        if (it + 1 < nit) {
            int k0 = (it + 1) * 16;
            pa = *(const float4*)&A [(m0 + am) * K + k0 + akq];
            pb = *(const float4*)&Bw[(n0 + am) * K + k0 + akq];
        }
        #pragma unroll
        for (int k = 0; k < 16; ++k) {
            ulonglong2 av  = *(const ulonglong2*)&As[k][ty << 2];
            ulonglong2 b01 = *(const ulonglong2*)&Bs[k][tx << 2];
            ulonglong2 b23 = *(const ulonglong2*)&Bs[k][(tx << 2) + 2];
            acc[0][0] = ffma2(av.x, b01.x, acc[0][0]);
            acc[0][1] = ffma2(av.x, b01.y, acc[0][1]);
            acc[0][2] = ffma2(av.x, b23.x, acc[0][2]);
            acc[0][3] = ffma2(av.x, b23.y, acc[0][3]);
            acc[1][0] = ffma2(av.y, b01.x, acc[1][0]);
            acc[1][1] = ffma2(av.y, b01.y, acc[1][1]);
            acc[1][2] = ffma2(av.y, b23.x, acc[1][2]);
            acc[1][3] = ffma2(av.y, b23.y, acc[1][3]);
        }
        __syncthreads();
    }

    float bb[4];
    #pragma unroll
    for (int n = 0; n < 4; n++) bb[n] = bias ? bias[n0 + tx * 4 + n] : 0.f;

    const int col0 = n0 + tx * 4;
    float R = 0.f;
    if (TRIG && n0 < 2 * CDIM) R = paramR[0];

    #pragma unroll
    for (int p = 0; p < 2; p++) {
        int r0 = m0 + (ty << 2) + 2 * p;
        float lo[4], hi[4];
        #pragma unroll
        for (int n = 0; n < 4; n++) up2(acc[p][n], lo[n], hi[n]);
        float4 o0 = make_float4(lo[0] + bb[0], lo[1] + bb[1], lo[2] + bb[2], lo[3] + bb[3]);
        float4 o1 = make_float4(hi[0] + bb[0], hi[1] + bb[1], hi[2] + bb[2], hi[3] + bb[3]);
        *(float4*)&C[(size_t)r0 * Ncols + col0]       = o0;
        *(float4*)&C[(size_t)(r0 + 1) * Ncols + col0] = o1;

        if (TRIG && n0 < 2 * CDIM) {
            float v0[4] = {o0.x, o0.y, o0.z, o0.w};
            float v1[4] = {o1.x, o1.y, o1.z, o1.w};
            float s0[4], c0[4], s1[4], c1[4];
            #pragma unroll
            for (int n = 0; n < 4; n++) {
                sincosf(R * v0[n], &s0[n], &c0[n]);
                sincosf(R * v1[n], &s1[n], &c1[n]);
            }
            if (n0 < CDIM) {
                int g0 = r0 * CDIM + col0, g1 = (r0 + 1) * CDIM + col0;
                *(float4*)&gqs[g0] = make_float4(s0[0], s0[1], s0[2], s0[3]);
                *(float4*)&gqc[g0] = make_float4(c0[0], c0[1], c0[2], c0[3]);
                *(float4*)&gqs[g1] = make_float4(s1[0], s1[1], s1[2], s1[3]);
                *(float4*)&gqc[g1] = make_float4(c1[0], c1[1], c1[2], c1[3]);
            } else {
                int kc0i = col0 - CDIM;
                int g0 = r0 * CDIM + kc0i, g1 = (r0 + 1) * CDIM + kc0i;
                *(float4*)&gknv[g0] = make_float4(-v0[0], -v0[1], -v0[2], -v0[3]);
                *(float4*)&gkns[g0] = make_float4(-s0[0], -s0[1], -s0[2], -s0[3]);
                *(float4*)&gkc [g0] = make_float4( c0[0],  c0[1],  c0[2],  c0[3]);
                *(float4*)&gknv[g1] = make_float4(-v1[0], -v1[1], -v1[2], -v1[3]);
                *(float4*)&gkns[g1] = make_float4(-s1[0], -s1[1], -s1[2], -s1[3]);
                *(float4*)&gkc [g1] = make_float4( c1[0],  c1[1],  c1[2],  c1[3]);
            }
        }
    }
}

// ---------------------------------------------------------------------------
// Fused Fourier attention (score + online PV). Block = (qtile, head, batch),
// 256 threads: q = tid&31, kg = tid>>5 (8 keys each).
// Q-side in [d4][q][4] chunk layout -> LDS.128 everywhere in the hot loop;
// K-side loads are warp-uniform broadcasts.
// ---------------------------------------------------------------------------
#define KREG 17408                       // [8][32][68] acc stash (>= 4*4096)
static const int ATTN_SMEM = (3 * 16 * CH + KREG + 8 * QT + QT) * 4;

__global__ __launch_bounds__(256, 2)
void fourier_attn3(const float* __restrict__ qkv,
                   const float* __restrict__ gqs, const float* __restrict__ gqc,
                   const float* __restrict__ gknv, const float* __restrict__ gkns,
                   const float* __restrict__ gkc,
                   const float* __restrict__ paramR, float* __restrict__ attout)
{
    extern __shared__ float sm[];
    float* sQv = sm;                      // [16][CH] chunked
    float* sQs = sQv + 16 * CH;
    float* sQc = sQs + 16 * CH;
    float* smK = sQc + 16 * CH;           // tile region / later acc stash
    float* sKv = smK;                     // [64][64]
    float* sKs = smK + 4096;
    float* sKc = smK + 8192;
    float* sV  = smK + 12288;
    float* sRed = smK + KREG;             // [8][32]

    const int tid = threadIdx.x;
    const int q = tid & 31, kg = tid >> 5;
    const int qt = blockIdx.x, h = blockIdx.y, b = blockIdx.z;
    const int tok0 = b * NSEQ, q0 = qt * QT;
    const float R = paramR[0];

    // q-side fill: 512 float4 chunks, coalesced reads, chunked smem layout
    for (int i = tid; i < QT * 16; i += 256) {
        int d4 = i & 15, qq = i >> 4;
        int g = (tok0 + q0 + qq) * CDIM + h * DH + d4 * 4;
        int sidx = d4 * CH + qq * 4;
        *(float4*)&sQs[sidx] = *(const float4*)&gqs[g];
        *(float4*)&sQc[sidx] = *(const float4*)&gqc[g];
        *(float4*)&sQv[sidx] = *(const float4*)&qkv[(tok0 + q0 + qq) * QKVD + h * DH + d4 * 4];
    }

    u64 acc[32];
    #pragma unroll
    for (int i = 0; i < 32; i++) acc[i] = 0ull;
    float rowsum = 0.f;

    for (int kc0 = 0; kc0 < NSEQ; kc0 += KT) {
        __syncthreads();
        for (int i = tid; i < KT * 16; i += 256) {
            int kk = i >> 4, dq = (i & 15) * 4;
            int g = (tok0 + kc0 + kk) * CDIM + h * DH + dq;
            int sidx = kk * DH + dq;
            *(float4*)&sKv[sidx] = *(const float4*)&gknv[g];
            *(float4*)&sKs[sidx] = *(const float4*)&gkns[g];
            *(float4*)&sKc[sidx] = *(const float4*)&gkc[g];
            *(float4*)&sV[sidx]  = *(const float4*)&qkv[(tok0 + kc0 + kk) * QKVD + 2 * CDIM + h * DH + dq];
        }
        __syncthreads();

        float np[8], dp[8];
        #pragma unroll
        for (int j = 0; j < 8; j++) { np[j] = 1.f; dp[j] = 1.f; }
        const int kb0 = kg * 8 * DH;

        #pragma unroll 2
        for (int d4 = 0; d4 < 16; d4++) {
            int qidx = d4 * CH + q * 4;
            ulonglong2 qv = *(const ulonglong2*)&sQv[qidx];
            ulonglong2 qs = *(const ulonglong2*)&sQs[qidx];
            ulonglong2 qc = *(const ulonglong2*)&sQc[qidx];
            #pragma unroll
            for (int j = 0; j < 8; j++) {
                int koff = kb0 + j * DH + d4 * 4;
                ulonglong2 kv = *(const ulonglong2*)&sKv[koff];
                ulonglong2 ks = *(const ulonglong2*)&sKs[koff];
                ulonglong2 kc = *(const ulonglong2*)&sKc[koff];
                u64 dfa = fadd2(qv.x, kv.x);                    // q - k (dims 0,1)
                u64 dfb = fadd2(qv.y, kv.y);                    // dims 2,3
                u64 nma = ffma2(qs.x, kc.x, fmul2(qc.x, ks.x)); // sin(R(q-k))
                u64 nmb = ffma2(qs.y, kc.y, fmul2(qc.y, ks.y));
                float d0, d1, d2, d3, n0, n1, n2, n3;
                up2(dfa, d0, d1); up2(dfb, d2, d3);
                up2(nma, n0, n1); up2(nmb, n2, n3);
                bool s0 = fabsf(d0) < T_SMALL, s1 = fabsf(d1) < T_SMALL;
                bool s2 = fabsf(d2) < T_SMALL, s3 = fabsf(d3) < T_SMALL;
                np[j] *= s0 ? R : n0;  dp[j] *= s0 ? 1.f : d0;
                np[j] *= s1 ? R : n1;  dp[j] *= s1 ? 1.f : d1;
                np[j] *= s2 ? R : n2;  dp[j] *= s2 ? 1.f : d2;
                np[j] *= s3 ? R : n3;  dp[j] *= s3 ? 1.f : d3;
            }
        }

        // a4 + online PV over this thread's 8 keys, all 64 dims
        #pragma unroll
        for (int j = 0; j < 8; j++) {
            float s = (dp[j] != 0.f) ? np[j] / dp[j] : 0.f;
            float s2 = s * s;
            float a4 = s2 * s2;
            rowsum += a4;
            u64 aa = pk2(a4, a4);
            const ulonglong2* vp = (const ulonglong2*)&sV[(kg * 8 + j) * DH];
            #pragma unroll
            for (int w = 0; w < 16; w++) {
                ulonglong2 vv = vp[w];                         // warp-uniform
                acc[2 * w]     = ffma2(aa, vv.x, acc[2 * w]);
                acc[2 * w + 1] = ffma2(aa, vv.y, acc[2 * w + 1]);
            }
        }
    }
    __syncthreads();

    // stash partials into freed K region
    sRed[kg * 32 + q] = rowsum;
    {
        float* myAcc = &smK[(kg * 32 + q) * 68];
        #pragma unroll
        for (int w = 0; w < 16; w++) {
            ulonglong2 vv; vv.x = acc[2 * w]; vv.y = acc[2 * w + 1];
            *(ulonglong2*)&myAcc[w * 4] = vv;
        }
    }
    __syncthreads();

    float ss = 0.f;
    #pragma unroll
    for (int r = 0; r < 8; r++) ss += sRed[r * 32 + q];
    float inv = 1.f / (ss + EPSF);
    u64 inv2 = pk2(inv, inv);

    // cross-warp reduce: thread (q,kg) produces dims kg*8..+8
    u64 o[4];
    #pragma unroll
    for (int i = 0; i < 4; i++) o[i] = 0ull;
    #pragma unroll
    for (int kgp = 0; kgp < 8; kgp++) {
        const float* src = &smK[(kgp * 32 + q) * 68 + kg * 8];
        ulonglong2 v0 = *(const ulonglong2*)src;
        ulonglong2 v1 = *(const ulonglong2*)(src + 4);
        o[0] = fadd2(o[0], v0.x); o[1] = fadd2(o[1], v0.y);
        o[2] = fadd2(o[2], v1.x); o[3] = fadd2(o[3], v1.y);
    }
    #pragma unroll
    for (int i = 0; i < 4; i++) o[i] = fmul2(o[i], inv2);

    float of[8];
    up2(o[0], of[0], of[1]); up2(o[1], of[2], of[3]);
    up2(o[2], of[4], of[5]); up2(o[3], of[6], of[7]);
    float* dst = &attout[(tok0 + q0 + q) * CDIM + h * DH + kg * 8];
    *(float4*)dst       = make_float4(of[0], of[1], of[2], of[3]);
    *(float4*)(dst + 4) = make_float4(of[4], of[5], of[6], of[7]);
}

extern "C" void kernel_launch(void* const* d_in, const int* in_sizes, int n_in,
                              void* d_out, int out_size)
{
    const float* x      = (const float*)d_in[0];
    const float* w_qkv  = (const float*)d_in[1];
    const float* w_proj = (const float*)d_in[2];
    const float* b_proj = (const float*)d_in[3];
    const float* paramR = (const float*)d_in[4];
    float* out = (float*)d_out;

    float *qkvbuf, *attbuf, *gqs, *gqc, *gknv, *gkns, *gkc;
    cudaGetSymbolAddress((void**)&qkvbuf, g_qkv);
    cudaGetSymbolAddress((void**)&attbuf, g_att);
    cudaGetSymbolAddress((void**)&gqs,  g_qs);
    cudaGetSymbolAddress((void**)&gqc,  g_qc);
    cudaGetSymbolAddress((void**)&gknv, g_knv);
    cudaGetSymbolAddress((void**)&gkns, g_kns);
    cudaGetSymbolAddress((void**)&gkc,  g_kc);

    cudaFuncSetAttribute(fourier_attn3, cudaFuncAttributeMaxDynamicSharedMemorySize,
                         ATTN_SMEM);

    // 1) qkv = x @ w_qkv^T + fused trig tables (384 blocks)
    gemm2f<true><<<dim3(QKVD / 64, TOKENS / 64), 256>>>(
        x, w_qkv, nullptr, qkvbuf, QKVD, CDIM,
        paramR, gqs, gqc, gknv, gkns, gkc);
    // 2) fused attention (256 blocks, 2/SM -> single wave)
    fourier_attn3<<<dim3(NSEQ / QT, HEADS, 4), 256, ATTN_SMEM>>>(
        qkvbuf, gqs, gqc, gknv, gkns, gkc, paramR, attbuf);
    // 3) out = att @ w_proj^T + b_proj (128 blocks, 64x64 tiles)
    gemm2f<false><<<dim3(CDIM / 64, TOKENS / 64), 256>>>(
        attbuf, w_proj, b_proj, out, CDIM, CDIM,
        nullptr, nullptr, nullptr, nullptr, nullptr, nullptr);
}

// round 6
// speedup vs baseline: 2.7222x; 2.7222x over previous
#include <cuda_runtime.h>
#include <math.h>

typedef unsigned long long u64;

#define TOKENS 1024
#define CDIM   512
#define QKVD   1536
#define NSEQ   256
#define HEADS  8
#define DH     64
#define QT     32
#define KT     64
#define EPSF   1e-6f
#define T_SMALL 0.009f
#define PADQ   66

// ---------------- packed f32x2 helpers ----------------
__device__ __forceinline__ u64 pk2(float lo, float hi) {
    u64 r; asm("mov.b64 %0,{%1,%2};" : "=l"(r) : "f"(lo), "f"(hi)); return r;
}
__device__ __forceinline__ void up2(u64 v, float& lo, float& hi) {
    asm("mov.b64 {%0,%1},%2;" : "=f"(lo), "=f"(hi) : "l"(v));
}
__device__ __forceinline__ u64 fadd2(u64 a, u64 b) {
    u64 r; asm("add.rn.f32x2 %0,%1,%2;" : "=l"(r) : "l"(a), "l"(b)); return r;
}
__device__ __forceinline__ u64 fmul2(u64 a, u64 b) {
    u64 r; asm("mul.rn.f32x2 %0,%1,%2;" : "=l"(r) : "l"(a), "l"(b)); return r;
}
__device__ __forceinline__ u64 ffma2(u64 a, u64 b, u64 c) {
    u64 r; asm("fma.rn.f32x2 %0,%1,%2,%3;" : "=l"(r) : "l"(a), "l"(b), "l"(c)); return r;
}

// ---------------- device scratch ----------------
__device__ float g_qkv[TOKENS * QKVD];
__device__ float g_att[TOKENS * CDIM];
__device__ float g_qs [TOKENS * CDIM];
__device__ float g_qc [TOKENS * CDIM];
__device__ float g_knv[TOKENS * CDIM];   // -k
__device__ float g_kns[TOKENS * CDIM];   // -sin(R k)
__device__ float g_kc [TOKENS * CDIM];   //  cos(R k)

// ---------------------------------------------------------------------------
// Trig precompute over q,k halves of qkv.
// ---------------------------------------------------------------------------
__global__ __launch_bounds__(256)
void trig_prep(const float* __restrict__ qkv, const float* __restrict__ paramR,
               float* __restrict__ gqs, float* __restrict__ gqc,
               float* __restrict__ gknv, float* __restrict__ gkns,
               float* __restrict__ gkc)
{
    int i = blockIdx.x * 256 + threadIdx.x;
    const float R = paramR[0];
    int tok = i >> 9, col = i & 511;
    float qv = qkv[tok * QKVD + col];
    float s, c;
    sincosf(R * qv, &s, &c);
    gqs[i] = s; gqc[i] = c;
    float kv = qkv[tok * QKVD + CDIM + col];
    sincosf(R * kv, &s, &c);
    gknv[i] = -kv; gkns[i] = -s; gkc[i] = c;
}

// ---------------------------------------------------------------------------
// FFMA2 GEMM (R4 proven layout): C = A[M,K]*Bw[N,K]^T (+bias).
// BM=64, BK=16, 256 threads. Per thread: 4 M-rows (2 f32x2 pairs) x TN N-cols.
// A pairs adjacent in As rows -> one LDS.128 per k, warp-broadcast.
// B scalar in smem (16B lane stride on reads); packed to {b,b} with MOVs.
// ---------------------------------------------------------------------------
template<int BN, int TN>
__global__ __launch_bounds__(256)
void gemm2f(const float* __restrict__ A, const float* __restrict__ Bw,
            const float* __restrict__ bias, float* __restrict__ C,
            int Ncols, int K)
{
    __shared__ __align__(16) float As[16][68];
    __shared__ __align__(16) float Bs[16][BN + 4];
    const int t  = threadIdx.x;
    const int m0 = blockIdx.y * 64;
    const int n0 = blockIdx.x * BN;
    const int tx = t & 15, ty = t >> 4;

    u64 acc[2][TN];
    #pragma unroll
    for (int p = 0; p < 2; p++)
        #pragma unroll
        for (int n = 0; n < TN; n++) acc[p][n] = 0ull;

    const int am = t >> 2, akq = (t & 3) << 2;       // A: 1 float4 / thread
    const int bn4 = t >> 2, bkq = (t & 3) << 2;      // B loads (BN=64 case)
    const int bn2 = t >> 3, bkp = (t & 7) << 1;      // B loads (BN=32 case)

    float4 pa, pb4; float2 pb2;
    pa = *(const float4*)&A[(m0 + am) * K + akq];
    if (TN == 4) pb4 = *(const float4*)&Bw[(n0 + bn4) * K + bkq];
    else         pb2 = *(const float2*)&Bw[(n0 + bn2) * K + bkp];

    const int nit = K / 16;
    for (int it = 0; it < nit; ++it) {
        As[akq + 0][am] = pa.x; As[akq + 1][am] = pa.y;
        As[akq + 2][am] = pa.z; As[akq + 3][am] = pa.w;
        if (TN == 4) {
            Bs[bkq + 0][bn4] = pb4.x; Bs[bkq + 1][bn4] = pb4.y;
            Bs[bkq + 2][bn4] = pb4.z; Bs[bkq + 3][bn4] = pb4.w;
        } else {
            Bs[bkp + 0][bn2] = pb2.x; Bs[bkp + 1][bn2] = pb2.y;
        }
        __syncthreads();
        if (it + 1 < nit) {
            int k0 = (it + 1) * 16;
            pa = *(const float4*)&A[(m0 + am) * K + k0 + akq];
            if (TN == 4) pb4 = *(const float4*)&Bw[(n0 + bn4) * K + k0 + bkq];
            else         pb2 = *(const float2*)&Bw[(n0 + bn2) * K + k0 + bkp];
        }
        #pragma unroll
        for (int k = 0; k < 16; ++k) {
            ulonglong2 av = *(const ulonglong2*)&As[k][ty << 2];
            if (TN == 4) {
                float4 bv = *(const float4*)&Bs[k][tx << 2];
                u64 b0 = pk2(bv.x, bv.x), b1 = pk2(bv.y, bv.y);
                u64 b2 = pk2(bv.z, bv.z), b3 = pk2(bv.w, bv.w);
                acc[0][0] = ffma2(av.x, b0, acc[0][0]);
                acc[0][1] = ffma2(av.x, b1, acc[0][1]);
                acc[0][2] = ffma2(av.x, b2, acc[0][2]);
                acc[0][3] = ffma2(av.x, b3, acc[0][3]);
                acc[1][0] = ffma2(av.y, b0, acc[1][0]);
                acc[1][1] = ffma2(av.y, b1, acc[1][1]);
                acc[1][2] = ffma2(av.y, b2, acc[1][2]);
                acc[1][3] = ffma2(av.y, b3, acc[1][3]);
            } else {
                float2 bv = *(const float2*)&Bs[k][tx << 1];
                u64 b0 = pk2(bv.x, bv.x), b1 = pk2(bv.y, bv.y);
                acc[0][0] = ffma2(av.x, b0, acc[0][0]);
                acc[0][1] = ffma2(av.x, b1, acc[0][1]);
                acc[1][0] = ffma2(av.y, b0, acc[1][0]);
                acc[1][1] = ffma2(av.y, b1, acc[1][1]);
            }
        }
        __syncthreads();
    }

    float bb[TN];
    #pragma unroll
    for (int n = 0; n < TN; n++) bb[n] = bias ? bias[n0 + tx * TN + n] : 0.f;

    #pragma unroll
    for (int p = 0; p < 2; p++) {
        int r0 = m0 + (ty << 2) + 2 * p;
        float lo[TN], hi[TN];
        #pragma unroll
        for (int n = 0; n < TN; n++) up2(acc[p][n], lo[n], hi[n]);
        if (TN == 4) {
            float4 o0 = make_float4(lo[0] + bb[0], lo[1] + bb[1], lo[2] + bb[2], lo[3] + bb[3]);
            float4 o1 = make_float4(hi[0] + bb[0], hi[1] + bb[1], hi[2] + bb[2], hi[3] + bb[3]);
            *(float4*)&C[(size_t)r0 * Ncols + n0 + tx * 4]       = o0;
            *(float4*)&C[(size_t)(r0 + 1) * Ncols + n0 + tx * 4] = o1;
        } else {
            float2 o0 = make_float2(lo[0] + bb[0], lo[1] + bb[1]);
            float2 o1 = make_float2(hi[0] + bb[0], hi[1] + bb[1]);
            *(float2*)&C[(size_t)r0 * Ncols + n0 + tx * 2]       = o0;
            *(float2*)&C[(size_t)(r0 + 1) * Ncols + n0 + tx * 2] = o1;
        }
    }
}

// ---------------------------------------------------------------------------
// Fused Fourier attention (R4 proven): score + online PV in one pass.
// Block = (qtile, head, batch), 256 threads. q = tid&31, kg = tid>>5.
// ---------------------------------------------------------------------------
#define KREG 17408                       // [8][32][68] acc region (>= 4*4096)
static const int ATTN_SMEM = (3 * QT * PADQ + KREG + 8 * QT + QT) * 4;

__global__ __launch_bounds__(256, 2)
void fourier_attn3(const float* __restrict__ qkv,
                   const float* __restrict__ gqs, const float* __restrict__ gqc,
                   const float* __restrict__ gknv, const float* __restrict__ gkns,
                   const float* __restrict__ gkc,
                   const float* __restrict__ paramR, float* __restrict__ attout)
{
    extern __shared__ float sm[];
    float* sQv = sm;                      // [32][66]
    float* sQs = sQv + QT * PADQ;
    float* sQc = sQs + QT * PADQ;
    float* smK = sQc + QT * PADQ;         // tile region / later acc region
    float* sKv = smK;                     // [64][64]
    float* sKs = smK + 4096;
    float* sKc = smK + 8192;
    float* sV  = smK + 12288;
    float* sRed = smK + KREG;             // [8][32]

    const int tid = threadIdx.x;
    const int q = tid & 31, kg = tid >> 5;
    const int qt = blockIdx.x, h = blockIdx.y, b = blockIdx.z;
    const int tok0 = b * NSEQ, q0 = qt * QT;
    const float R = paramR[0];

    // q-side fill (pure copies from precomputed trig)
    for (int i = tid; i < QT * 32; i += 256) {
        int qq = i >> 5, d2 = i & 31;
        int g = (tok0 + q0 + qq) * CDIM + h * DH + d2 * 2;
        int sidx = qq * PADQ + d2 * 2;
        *(float2*)&sQs[sidx] = *(const float2*)&gqs[g];
        *(float2*)&sQc[sidx] = *(const float2*)&gqc[g];
        *(float2*)&sQv[sidx] = *(const float2*)&qkv[(tok0 + q0 + qq) * QKVD + h * DH + d2 * 2];
    }

    u64 acc[32];
    #pragma unroll
    for (int i = 0; i < 32; i++) acc[i] = 0ull;
    float rowsum = 0.f;

    for (int kc0 = 0; kc0 < NSEQ; kc0 += KT) {
        __syncthreads();
        for (int i = tid; i < KT * 16; i += 256) {
            int kk = i >> 4, dq = (i & 15) * 4;
            int g = (tok0 + kc0 + kk) * CDIM + h * DH + dq;
            int sidx = kk * DH + dq;
            *(float4*)&sKv[sidx] = *(const float4*)&gknv[g];
            *(float4*)&sKs[sidx] = *(const float4*)&gkns[g];
            *(float4*)&sKc[sidx] = *(const float4*)&gkc[g];
            *(float4*)&sV[sidx]  = *(const float4*)&qkv[(tok0 + kc0 + kk) * QKVD + 2 * CDIM + h * DH + dq];
        }
        __syncthreads();

        // ---- score for this thread's 8 keys ----
        float np[8], dp[8];
        #pragma unroll
        for (int j = 0; j < 8; j++) { np[j] = 1.f; dp[j] = 1.f; }
        const int kb0 = kg * 8 * DH;

        #pragma unroll 4
        for (int d2 = 0; d2 < 32; d2++) {
            u64 qv2 = *(const u64*)&sQv[q * PADQ + d2 * 2];
            u64 qs2 = *(const u64*)&sQs[q * PADQ + d2 * 2];
            u64 qc2 = *(const u64*)&sQc[q * PADQ + d2 * 2];
            #pragma unroll
            for (int j = 0; j < 8; j++) {
                int kidx = kb0 + j * DH + d2 * 2;
                u64 kv2 = *(const u64*)&sKv[kidx];
                u64 ks2 = *(const u64*)&sKs[kidx];
                u64 kc2 = *(const u64*)&sKc[kidx];
                u64 diff2 = fadd2(qv2, kv2);                   // q - k
                u64 num2  = ffma2(qs2, kc2, fmul2(qc2, ks2));  // sin(R(q-k))
                float d0, d1, n0v, n1v;
                up2(diff2, d0, d1); up2(num2, n0v, n1v);
                bool s0 = fabsf(d0) < T_SMALL, s1 = fabsf(d1) < T_SMALL;
                np[j] *= s0 ? R : n0v;
                dp[j] *= s0 ? 1.f : d0;
                np[j] *= s1 ? R : n1v;
                dp[j] *= s1 ? 1.f : d1;
            }
        }

        // ---- a4 + online PV over this thread's keys, all 64 dims ----
        #pragma unroll
        for (int j = 0; j < 8; j++) {
            float s = (dp[j] != 0.f) ? np[j] / dp[j] : 0.f;
            float s2 = s * s;
            float a4 = s2 * s2;
            rowsum += a4;
            u64 aa = pk2(a4, a4);
            const ulonglong2* vp = (const ulonglong2*)&sV[(kg * 8 + j) * DH];
            #pragma unroll
            for (int w = 0; w < 16; w++) {
                ulonglong2 vv = vp[w];                         // warp-uniform
                acc[2 * w]     = ffma2(aa, vv.x, acc[2 * w]);
                acc[2 * w + 1] = ffma2(aa, vv.y, acc[2 * w + 1]);
            }
        }
    }
    __syncthreads();

    // stash partials: rowsum and 64-dim acc into freed K region
    sRed[kg * 32 + q] = rowsum;
    {
        float* myAcc = &smK[(kg * 32 + q) * 68];
        #pragma unroll
        for (int w = 0; w < 16; w++) {
            ulonglong2 vv; vv.x = acc[2 * w]; vv.y = acc[2 * w + 1];
            *(ulonglong2*)&myAcc[w * 4] = vv;
        }
    }
    __syncthreads();

    // normalization factor
    float ss = 0.f;
    #pragma unroll
    for (int r = 0; r < 8; r++) ss += sRed[r * 32 + q];
    float inv = 1.f / (ss + EPSF);
    u64 inv2 = pk2(inv, inv);

    // cross-warp reduce: thread (q,kg) produces dims kg*8..+8
    u64 o[4];
    #pragma unroll
    for (int i = 0; i < 4; i++) o[i] = 0ull;
    #pragma unroll
    for (int kgp = 0; kgp < 8; kgp++) {
        const float* src = &smK[(kgp * 32 + q) * 68 + kg * 8];
        ulonglong2 v0 = *(const ulonglong2*)src;
        ulonglong2 v1 = *(const ulonglong2*)(src + 4);
        o[0] = fadd2(o[0], v0.x); o[1] = fadd2(o[1], v0.y);
        o[2] = fadd2(o[2], v1.x); o[3] = fadd2(o[3], v1.y);
    }
    #pragma unroll
    for (int i = 0; i < 4; i++) o[i] = fmul2(o[i], inv2);

    float of[8];
    up2(o[0], of[0], of[1]); up2(o[1], of[2], of[3]);
    up2(o[2], of[4], of[5]); up2(o[3], of[6], of[7]);
    float* dst = &attout[(tok0 + q0 + q) * CDIM + h * DH + kg * 8];
    *(float4*)dst       = make_float4(of[0], of[1], of[2], of[3]);
    *(float4*)(dst + 4) = make_float4(of[4], of[5], of[6], of[7]);
}

extern "C" void kernel_launch(void* const* d_in, const int* in_sizes, int n_in,
                              void* d_out, int out_size)
{
    const float* x      = (const float*)d_in[0];
    const float* w_qkv  = (const float*)d_in[1];
    const float* w_proj = (const float*)d_in[2];
    const float* b_proj = (const float*)d_in[3];
    const float* paramR = (const float*)d_in[4];
    float* out = (float*)d_out;

    float *qkvbuf, *attbuf, *gqs, *gqc, *gknv, *gkns, *gkc;
    cudaGetSymbolAddress((void**)&qkvbuf, g_qkv);
    cudaGetSymbolAddress((void**)&attbuf, g_att);
    cudaGetSymbolAddress((void**)&gqs,  g_qs);
    cudaGetSymbolAddress((void**)&gqc,  g_qc);
    cudaGetSymbolAddress((void**)&gknv, g_knv);
    cudaGetSymbolAddress((void**)&gkns, g_kns);
    cudaGetSymbolAddress((void**)&gkc,  g_kc);

    cudaFuncSetAttribute(fourier_attn3, cudaFuncAttributeMaxDynamicSharedMemorySize,
                         ATTN_SMEM);

    // 1) qkv = x @ w_qkv^T (1024x1536, K=512): 64x64 tiles -> 384 blocks, 256 thr
    gemm2f<64, 4><<<dim3(QKVD / 64, TOKENS / 64), 256>>>(x, w_qkv, nullptr,
                                                         qkvbuf, QKVD, CDIM);
    // 2) trig precompute
    trig_prep<<<TOKENS * CDIM / 256, 256>>>(qkvbuf, paramR, gqs, gqc, gknv, gkns, gkc);
    // 3) fused attention (256 blocks, 2/SM resident -> single wave)
    fourier_attn3<<<dim3(NSEQ / QT, HEADS, 4), 256, ATTN_SMEM>>>(
        qkvbuf, gqs, gqc, gknv, gkns, gkc, paramR, attbuf);
    // 4) out = att @ w_proj^T + b_proj: 64x64 tiles -> 128 blocks, 256 thr
    gemm2f<64, 4><<<dim3(CDIM / 64, TOKENS / 64), 256>>>(attbuf, w_proj, b_proj,
                                                         out, CDIM, CDIM);
}

// round 8
// speedup vs baseline: 3.5170x; 1.2920x over previous
#include <cuda_runtime.h>
#include <cuda_bf16.h>
#include <math.h>
#include <stdint.h>

typedef unsigned long long u64;

#define TOKENS 1024
#define CDIM   512
#define QKVD   1536
#define NSEQ   256
#define HEADS  8
#define DH     64
#define QT     32
#define KT     64
#define EPSF   1e-6f
#define T_SMALL 0.009f
#define PADQ   66

// ---------------- packed f32x2 helpers (attention) ----------------
__device__ __forceinline__ u64 pk2(float lo, float hi) {
    u64 r; asm("mov.b64 %0,{%1,%2};" : "=l"(r) : "f"(lo), "f"(hi)); return r;
}
__device__ __forceinline__ void up2(u64 v, float& lo, float& hi) {
    asm("mov.b64 {%0,%1},%2;" : "=f"(lo), "=f"(hi) : "l"(v));
}
__device__ __forceinline__ u64 fadd2(u64 a, u64 b) {
    u64 r; asm("add.rn.f32x2 %0,%1,%2;" : "=l"(r) : "l"(a), "l"(b)); return r;
}
__device__ __forceinline__ u64 fmul2(u64 a, u64 b) {
    u64 r; asm("mul.rn.f32x2 %0,%1,%2;" : "=l"(r) : "l"(a), "l"(b)); return r;
}
__device__ __forceinline__ u64 ffma2(u64 a, u64 b, u64 c) {
    u64 r; asm("fma.rn.f32x2 %0,%1,%2,%3;" : "=l"(r) : "l"(a), "l"(b), "l"(c)); return r;
}

__device__ __forceinline__ uint32_t smem_u32(const void* p) {
    uint32_t a;
    asm("{ .reg .u64 t; cvta.to.shared.u64 t, %1; cvt.u32.u64 %0, t; }"
        : "=r"(a) : "l"(p));
    return a;
}

// ---------------- device scratch ----------------
__device__ float g_qkv[TOKENS * QKVD];
__device__ float g_att[TOKENS * CDIM];
__device__ float g_qs [TOKENS * CDIM];
__device__ float g_qc [TOKENS * CDIM];
__device__ float g_knv[TOKENS * CDIM];
__device__ float g_kns[TOKENS * CDIM];
__device__ float g_kc [TOKENS * CDIM];
__device__ __nv_bfloat16 g_xh [TOKENS * CDIM];
__device__ __nv_bfloat16 g_xl [TOKENS * CDIM];
__device__ __nv_bfloat16 g_wqh[QKVD * CDIM];
__device__ __nv_bfloat16 g_wql[QKVD * CDIM];
__device__ __nv_bfloat16 g_wph[CDIM * CDIM];
__device__ __nv_bfloat16 g_wpl[CDIM * CDIM];
__device__ __nv_bfloat16 g_ath[TOKENS * CDIM];
__device__ __nv_bfloat16 g_atl[TOKENS * CDIM];

// ---------------------------------------------------------------------------
// split fp32 -> bf16 hi + bf16 lo(residual)
// ---------------------------------------------------------------------------
__global__ __launch_bounds__(256)
void split_bf16(const float* __restrict__ a, __nv_bfloat16* __restrict__ h,
                __nv_bfloat16* __restrict__ l, int n)
{
    int i = blockIdx.x * 256 + threadIdx.x;
    if (i < n) {
        float v = a[i];
        __nv_bfloat16 hh = __float2bfloat16(v);
        h[i] = hh;
        l[i] = __float2bfloat16(v - __bfloat162float(hh));
    }
}

// ---------------------------------------------------------------------------
// HMMA split-bf16 GEMM: C[M,Ncols] = A[M,512]*B[N,512]^T (+bias), fp32 acc.
// 64x64 CTA tile, 128 threads (4 warps x 32x32). mma.sync m16n8k16 bf16.
// 3 split products: ah*bh + ah*bl + al*bh (al*bl dropped, ~2^-18 rel).
// K chunks of 64, cp.async double buffer. smem row stride 72 bf16 (144B):
// fragment LDS banks = 4g+tg -> conflict-free.
// ---------------------------------------------------------------------------
#define GS       144                    // smem row stride bytes (72 bf16)
#define OFF_AL   9216                   // 64 rows * 144
#define OFF_BH   18432
#define OFF_BL   27648
#define BUFSZ    36864
#define HG_SMEM  (2 * BUFSZ)

__device__ __forceinline__ void mma_bf16(float* c, const uint32_t* a,
                                         const uint32_t* b) {
    asm volatile(
        "mma.sync.aligned.m16n8k16.row.col.f32.bf16.bf16.f32 "
        "{%0,%1,%2,%3}, {%4,%5,%6,%7}, {%8,%9}, {%0,%1,%2,%3};"
        : "+f"(c[0]), "+f"(c[1]), "+f"(c[2]), "+f"(c[3])
        : "r"(a[0]), "r"(a[1]), "r"(a[2]), "r"(a[3]), "r"(b[0]), "r"(b[1]));
}
__device__ __forceinline__ void cp16(uint32_t s, const void* g) {
    asm volatile("cp.async.cg.shared.global [%0], [%1], 16;" :: "r"(s), "l"(g));
}
__device__ __forceinline__ uint32_t lds32(uint32_t a) {
    uint32_t v; asm("ld.shared.b32 %0,[%1];" : "=r"(v) : "r"(a)); return v;
}

__global__ __launch_bounds__(128)
void hmma_gemm(const __nv_bfloat16* __restrict__ Ah, const __nv_bfloat16* __restrict__ Al,
               const __nv_bfloat16* __restrict__ Bh, const __nv_bfloat16* __restrict__ Bl,
               const float* __restrict__ bias, float* __restrict__ C, int Ncols)
{
    extern __shared__ char smem[];
    const uint32_t sb = smem_u32(smem);
    const int tid = threadIdx.x;
    const int w = tid >> 5, lane = tid & 31;
    const int g = lane >> 2, tg = lane & 3;
    const int m0 = blockIdx.y * 64, n0 = blockIdx.x * 64;
    const int wm = (w >> 1) * 32, wn = (w & 1) * 32;

    float acc[2][4][4];
    #pragma unroll
    for (int mt = 0; mt < 2; mt++)
        #pragma unroll
        for (int nt = 0; nt < 4; nt++)
            #pragma unroll
            for (int i = 0; i < 4; i++) acc[mt][nt][i] = 0.f;

    // ---- async chunk fill: 4 matrices x 64x64 bf16, 16B per cp ----
    #define ISSUE_CHUNK(cc, pp) do {                                          \
        int k0_ = (cc) * 64;                                                  \
        uint32_t dst_ = sb + (pp) * BUFSZ;                                    \
        _Pragma("unroll")                                                     \
        for (int v_ = 0; v_ < 4; v_++) {                                      \
            int f_ = v_ * 128 + tid;                                          \
            int row_ = f_ >> 3, cg_ = f_ & 7;                                 \
            uint32_t so_ = row_ * GS + cg_ * 16;                              \
            size_t ga_ = (size_t)(m0 + row_) * CDIM + k0_ + cg_ * 8;          \
            size_t gb_ = (size_t)(n0 + row_) * CDIM + k0_ + cg_ * 8;          \
            cp16(dst_ + so_,          Ah + ga_);                              \
            cp16(dst_ + OFF_AL + so_, Al + ga_);                              \
            cp16(dst_ + OFF_BH + so_, Bh + gb_);                              \
            cp16(dst_ + OFF_BL + so_, Bl + gb_);                              \
        }                                                                     \
        asm volatile("cp.async.commit_group;");                               \
    } while (0)

    ISSUE_CHUNK(0, 0);
    ISSUE_CHUNK(1, 1);

    for (int c = 0; c < 8; ++c) {
        if (c == 7) asm volatile("cp.async.wait_group 0;" ::: "memory");
        else        asm volatile("cp.async.wait_group 1;" ::: "memory");
        __syncthreads();

        const uint32_t buf = sb + (c & 1) * BUFSZ;
        #pragma unroll
        for (int ks = 0; ks < 4; ks++) {
            uint32_t aH[2][4], aL[2][4], bH[4][2], bL[4][2];
            #pragma unroll
            for (int mt = 0; mt < 2; mt++) {
                uint32_t ad = buf + (wm + mt * 16 + g) * GS + ks * 32 + tg * 4;
                aH[mt][0] = lds32(ad);
                aH[mt][1] = lds32(ad + 8 * GS);
                aH[mt][2] = lds32(ad + 16);
                aH[mt][3] = lds32(ad + 8 * GS + 16);
                uint32_t al = ad + OFF_AL;
                aL[mt][0] = lds32(al);
                aL[mt][1] = lds32(al + 8 * GS);
                aL[mt][2] = lds32(al + 16);
                aL[mt][3] = lds32(al + 8 * GS + 16);
            }
            #pragma unroll
            for (int nt = 0; nt < 4; nt++) {
                uint32_t bd = buf + OFF_BH + (wn + nt * 8 + g) * GS + ks * 32 + tg * 4;
                bH[nt][0] = lds32(bd);
                bH[nt][1] = lds32(bd + 16);
                uint32_t bl = bd + (OFF_BL - OFF_BH);
                bL[nt][0] = lds32(bl);
                bL[nt][1] = lds32(bl + 16);
            }
            #pragma unroll
            for (int mt = 0; mt < 2; mt++)
                #pragma unroll
                for (int nt = 0; nt < 4; nt++) {
                    mma_bf16(acc[mt][nt], aH[mt], bH[nt]);
                    mma_bf16(acc[mt][nt], aH[mt], bL[nt]);
                    mma_bf16(acc[mt][nt], aL[mt], bH[nt]);
                }
        }
        __syncthreads();
        if (c + 2 < 8) ISSUE_CHUNK(c + 2, c & 1);
    }

    // epilogue: c0,c1 = (row g, col tg*2,+1); c2,c3 = (row g+8)
    #pragma unroll
    for (int mt = 0; mt < 2; mt++) {
        int r0 = m0 + wm + mt * 16 + g;
        #pragma unroll
        for (int nt = 0; nt < 4; nt++) {
            int col = n0 + wn + nt * 8 + tg * 2;
            float b0 = 0.f, b1 = 0.f;
            if (bias) { b0 = bias[col]; b1 = bias[col + 1]; }
            *(float2*)&C[(size_t)r0 * Ncols + col] =
                make_float2(acc[mt][nt][0] + b0, acc[mt][nt][1] + b1);
            *(float2*)&C[(size_t)(r0 + 8) * Ncols + col] =
                make_float2(acc[mt][nt][2] + b0, acc[mt][nt][3] + b1);
        }
    }
    #undef ISSUE_CHUNK
}

// ---------------------------------------------------------------------------
// Trig precompute over q,k halves of qkv. (unchanged, proven)
// ---------------------------------------------------------------------------
__global__ __launch_bounds__(256)
void trig_prep(const float* __restrict__ qkv, const float* __restrict__ paramR,
               float* __restrict__ gqs, float* __restrict__ gqc,
               float* __restrict__ gknv, float* __restrict__ gkns,
               float* __restrict__ gkc)
{
    int i = blockIdx.x * 256 + threadIdx.x;
    const float R = paramR[0];
    int tok = i >> 9, col = i & 511;
    float qv = qkv[tok * QKVD + col];
    float s, c;
    sincosf(R * qv, &s, &c);
    gqs[i] = s; gqc[i] = c;
    float kv = qkv[tok * QKVD + CDIM + col];
    sincosf(R * kv, &s, &c);
    gknv[i] = -kv; gkns[i] = -s; gkc[i] = c;
}

// ---------------------------------------------------------------------------
// Fused Fourier attention (R6 proven, unchanged).
// ---------------------------------------------------------------------------
#define KREG 17408
static const int ATTN_SMEM = (3 * QT * PADQ + KREG + 8 * QT + QT) * 4;

__global__ __launch_bounds__(256, 2)
void fourier_attn3(const float* __restrict__ qkv,
                   const float* __restrict__ gqs, const float* __restrict__ gqc,
                   const float* __restrict__ gknv, const float* __restrict__ gkns,
                   const float* __restrict__ gkc,
                   const float* __restrict__ paramR, float* __restrict__ attout)
{
    extern __shared__ float sm[];
    float* sQv = sm;
    float* sQs = sQv + QT * PADQ;
    float* sQc = sQs + QT * PADQ;
    float* smK = sQc + QT * PADQ;
    float* sKv = smK;
    float* sKs = smK + 4096;
    float* sKc = smK + 8192;
    float* sV  = smK + 12288;
    float* sRed = smK + KREG;

    const int tid = threadIdx.x;
    const int q = tid & 31, kg = tid >> 5;
    const int qt = blockIdx.x, h = blockIdx.y, b = blockIdx.z;
    const int tok0 = b * NSEQ, q0 = qt * QT;
    const float R = paramR[0];

    for (int i = tid; i < QT * 32; i += 256) {
        int qq = i >> 5, d2 = i & 31;
        int g = (tok0 + q0 + qq) * CDIM + h * DH + d2 * 2;
        int sidx = qq * PADQ + d2 * 2;
        *(float2*)&sQs[sidx] = *(const float2*)&gqs[g];
        *(float2*)&sQc[sidx] = *(const float2*)&gqc[g];
        *(float2*)&sQv[sidx] = *(const float2*)&qkv[(tok0 + q0 + qq) * QKVD + h * DH + d2 * 2];
    }

    u64 acc[32];
    #pragma unroll
    for (int i = 0; i < 32; i++) acc[i] = 0ull;
    float rowsum = 0.f;

    for (int kc0 = 0; kc0 < NSEQ; kc0 += KT) {
        __syncthreads();
        for (int i = tid; i < KT * 16; i += 256) {
            int kk = i >> 4, dq = (i & 15) * 4;
            int g = (tok0 + kc0 + kk) * CDIM + h * DH + dq;
            int sidx = kk * DH + dq;
            *(float4*)&sKv[sidx] = *(const float4*)&gknv[g];
            *(float4*)&sKs[sidx] = *(const float4*)&gkns[g];
            *(float4*)&sKc[sidx] = *(const float4*)&gkc[g];
            *(float4*)&sV[sidx]  = *(const float4*)&qkv[(tok0 + kc0 + kk) * QKVD + 2 * CDIM + h * DH + dq];
        }
        __syncthreads();

        float np[8], dp[8];
        #pragma unroll
        for (int j = 0; j < 8; j++) { np[j] = 1.f; dp[j] = 1.f; }
        const int kb0 = kg * 8 * DH;

        #pragma unroll 4
        for (int d2 = 0; d2 < 32; d2++) {
            u64 qv2 = *(const u64*)&sQv[q * PADQ + d2 * 2];
            u64 qs2 = *(const u64*)&sQs[q * PADQ + d2 * 2];
            u64 qc2 = *(const u64*)&sQc[q * PADQ + d2 * 2];
            #pragma unroll
            for (int j = 0; j < 8; j++) {
                int kidx = kb0 + j * DH + d2 * 2;
                u64 kv2 = *(const u64*)&sKv[kidx];
                u64 ks2 = *(const u64*)&sKs[kidx];
                u64 kc2 = *(const u64*)&sKc[kidx];
                u64 diff2 = fadd2(qv2, kv2);
                u64 num2  = ffma2(qs2, kc2, fmul2(qc2, ks2));
                float d0, d1, n0v, n1v;
                up2(diff2, d0, d1); up2(num2, n0v, n1v);
                bool s0 = fabsf(d0) < T_SMALL, s1 = fabsf(d1) < T_SMALL;
                np[j] *= s0 ? R : n0v;
                dp[j] *= s0 ? 1.f : d0;
                np[j] *= s1 ? R : n1v;
                dp[j] *= s1 ? 1.f : d1;
            }
        }

        #pragma unroll
        for (int j = 0; j < 8; j++) {
            float s = (dp[j] != 0.f) ? np[j] / dp[j] : 0.f;
            float s2 = s * s;
            float a4 = s2 * s2;
            rowsum += a4;
            u64 aa = pk2(a4, a4);
            const ulonglong2* vp = (const ulonglong2*)&sV[(kg * 8 + j) * DH];
            #pragma unroll
            for (int w = 0; w < 16; w++) {
                ulonglong2 vv = vp[w];
                acc[2 * w]     = ffma2(aa, vv.x, acc[2 * w]);
                acc[2 * w + 1] = ffma2(aa, vv.y, acc[2 * w + 1]);
            }
        }
    }
    __syncthreads();

    sRed[kg * 32 + q] = rowsum;
    {
        float* myAcc = &smK[(kg * 32 + q) * 68];
        #pragma unroll
        for (int w = 0; w < 16; w++) {
            ulonglong2 vv; vv.x = acc[2 * w]; vv.y = acc[2 * w + 1];
            *(ulonglong2*)&myAcc[w * 4] = vv;
        }
    }
    __syncthreads();

    float ss = 0.f;
    #pragma unroll
    for (int r = 0; r < 8; r++) ss += sRed[r * 32 + q];
    float inv = 1.f / (ss + EPSF);
    u64 inv2 = pk2(inv, inv);

    u64 o[4];
    #pragma unroll
    for (int i = 0; i < 4; i++) o[i] = 0ull;
    #pragma unroll
    for (int kgp = 0; kgp < 8; kgp++) {
        const float* src = &smK[(kgp * 32 + q) * 68 + kg * 8];
        ulonglong2 v0 = *(const ulonglong2*)src;
        ulonglong2 v1 = *(const ulonglong2*)(src + 4);
        o[0] = fadd2(o[0], v0.x); o[1] = fadd2(o[1], v0.y);
        o[2] = fadd2(o[2], v1.x); o[3] = fadd2(o[3], v1.y);
    }
    #pragma unroll
    for (int i = 0; i < 4; i++) o[i] = fmul2(o[i], inv2);

    float of[8];
    up2(o[0], of[0], of[1]); up2(o[1], of[2], of[3]);
    up2(o[2], of[4], of[5]); up2(o[3], of[6], of[7]);
    float* dst = &attout[(tok0 + q0 + q) * CDIM + h * DH + kg * 8];
    *(float4*)dst       = make_float4(of[0], of[1], of[2], of[3]);
    *(float4*)(dst + 4) = make_float4(of[4], of[5], of[6], of[7]);
}

extern "C" void kernel_launch(void* const* d_in, const int* in_sizes, int n_in,
                              void* d_out, int out_size)
{
    const float* x      = (const float*)d_in[0];
    const float* w_qkv  = (const float*)d_in[1];
    const float* w_proj = (const float*)d_in[2];
    const float* b_proj = (const float*)d_in[3];
    const float* paramR = (const float*)d_in[4];
    float* out = (float*)d_out;

    float *qkvbuf, *attbuf, *gqs, *gqc, *gknv, *gkns, *gkc;
    __nv_bfloat16 *xh, *xl, *wqh, *wql, *wph, *wpl, *ath, *atl;
    cudaGetSymbolAddress((void**)&qkvbuf, g_qkv);
    cudaGetSymbolAddress((void**)&attbuf, g_att);
    cudaGetSymbolAddress((void**)&gqs,  g_qs);
    cudaGetSymbolAddress((void**)&gqc,  g_qc);
    cudaGetSymbolAddress((void**)&gknv, g_knv);
    cudaGetSymbolAddress((void**)&gkns, g_kns);
    cudaGetSymbolAddress((void**)&gkc,  g_kc);
    cudaGetSymbolAddress((void**)&xh,  g_xh);
    cudaGetSymbolAddress((void**)&xl,  g_xl);
    cudaGetSymbolAddress((void**)&wqh, g_wqh);
    cudaGetSymbolAddress((void**)&wql, g_wql);
    cudaGetSymbolAddress((void**)&wph, g_wph);
    cudaGetSymbolAddress((void**)&wpl, g_wpl);
    cudaGetSymbolAddress((void**)&ath, g_ath);
    cudaGetSymbolAddress((void**)&atl, g_atl);

    cudaFuncSetAttribute(fourier_attn3, cudaFuncAttributeMaxDynamicSharedMemorySize,
                         ATTN_SMEM);
    cudaFuncSetAttribute(hmma_gemm, cudaFuncAttributeMaxDynamicSharedMemorySize,
                         HG_SMEM);

    // 0) split inputs to bf16 hi/lo
    split_bf16<<<TOKENS * CDIM / 256, 256>>>(x, xh, xl, TOKENS * CDIM);
    split_bf16<<<QKVD * CDIM / 256, 256>>>(w_qkv, wqh, wql, QKVD * CDIM);
    split_bf16<<<CDIM * CDIM / 256, 256>>>(w_proj, wph, wpl, CDIM * CDIM);

    // 1) qkv = x @ w_qkv^T via HMMA (384 CTAs of 128 thr)
    hmma_gemm<<<dim3(QKVD / 64, TOKENS / 64), 128, HG_SMEM>>>(
        xh, xl, wqh, wql, nullptr, qkvbuf, QKVD);

    // 2) trig precompute
    trig_prep<<<TOKENS * CDIM / 256, 256>>>(qkvbuf, paramR, gqs, gqc, gknv, gkns, gkc);

    // 3) fused attention (unchanged)
    fourier_attn3<<<dim3(NSEQ / QT, HEADS, 4), 256, ATTN_SMEM>>>(
        qkvbuf, gqs, gqc, gknv, gkns, gkc, paramR, attbuf);

    // 4) split attention output, then proj via HMMA (128 CTAs)
    split_bf16<<<TOKENS * CDIM / 256, 256>>>(attbuf, ath, atl, TOKENS * CDIM);
    hmma_gemm<<<dim3(CDIM / 64, TOKENS / 64), 128, HG_SMEM>>>(
        ath, atl, wph, wpl, b_proj, out, CDIM);
}

// round 9
// speedup vs baseline: 3.7974x; 1.0797x over previous
#include <cuda_runtime.h>
#include <cuda_bf16.h>
#include <math.h>
#include <stdint.h>

typedef unsigned long long u64;

#define TOKENS 1024
#define CDIM   512
#define QKVD   1536
#define NSEQ   256
#define HEADS  8
#define DH     64
#define QT     32
#define KT     64
#define EPSF   1e-6f
#define T_SMALL 0.009f
#define CH     132                      // q-side chunk stride (floats)

// ---------------- packed f32x2 helpers ----------------
__device__ __forceinline__ u64 pk2(float lo, float hi) {
    u64 r; asm("mov.b64 %0,{%1,%2};" : "=l"(r) : "f"(lo), "f"(hi)); return r;
}
__device__ __forceinline__ void up2(u64 v, float& lo, float& hi) {
    asm("mov.b64 {%0,%1},%2;" : "=f"(lo), "=f"(hi) : "l"(v));
}
__device__ __forceinline__ u64 fadd2(u64 a, u64 b) {
    u64 r; asm("add.rn.f32x2 %0,%1,%2;" : "=l"(r) : "l"(a), "l"(b)); return r;
}
__device__ __forceinline__ u64 fmul2(u64 a, u64 b) {
    u64 r; asm("mul.rn.f32x2 %0,%1,%2;" : "=l"(r) : "l"(a), "l"(b)); return r;
}
__device__ __forceinline__ u64 ffma2(u64 a, u64 b, u64 c) {
    u64 r; asm("fma.rn.f32x2 %0,%1,%2,%3;" : "=l"(r) : "l"(a), "l"(b), "l"(c)); return r;
}
__device__ __forceinline__ uint32_t smem_u32(const void* p) {
    uint32_t a;
    asm("{ .reg .u64 t; cvta.to.shared.u64 t, %1; cvt.u32.u64 %0, t; }"
        : "=r"(a) : "l"(p));
    return a;
}

// ---------------- device scratch ----------------
__device__ float g_qkv[TOKENS * QKVD];
__device__ float g_qs [TOKENS * CDIM];
__device__ float g_qc [TOKENS * CDIM];
__device__ float g_knv[TOKENS * CDIM];
__device__ float g_kns[TOKENS * CDIM];
__device__ float g_kc [TOKENS * CDIM];
__device__ __nv_bfloat16 g_xh [TOKENS * CDIM];
__device__ __nv_bfloat16 g_xl [TOKENS * CDIM];
__device__ __nv_bfloat16 g_wqh[QKVD * CDIM];
__device__ __nv_bfloat16 g_wql[QKVD * CDIM];
__device__ __nv_bfloat16 g_wph[CDIM * CDIM];
__device__ __nv_bfloat16 g_wpl[CDIM * CDIM];
__device__ __nv_bfloat16 g_ath[TOKENS * CDIM];
__device__ __nv_bfloat16 g_atl[TOKENS * CDIM];

// ---------------------------------------------------------------------------
// Merged split of all three fp32 inputs -> bf16 hi/lo.
// ---------------------------------------------------------------------------
#define NX (TOKENS * CDIM)
#define NQ (QKVD * CDIM)
#define NP (CDIM * CDIM)
__global__ __launch_bounds__(256)
void split_all(const float* __restrict__ x, const float* __restrict__ wq,
               const float* __restrict__ wp,
               __nv_bfloat16* __restrict__ xh, __nv_bfloat16* __restrict__ xl,
               __nv_bfloat16* __restrict__ wqh, __nv_bfloat16* __restrict__ wql,
               __nv_bfloat16* __restrict__ wph, __nv_bfloat16* __restrict__ wpl)
{
    int i = blockIdx.x * 256 + threadIdx.x;
    const float* src; __nv_bfloat16 *h, *l; int off;
    if (i < NX)           { src = x;  h = xh;  l = xl;  off = i; }
    else if (i < NX + NQ) { src = wq; h = wqh; l = wql; off = i - NX; }
    else                  { src = wp; h = wph; l = wpl; off = i - NX - NQ; }
    float v = src[off];
    __nv_bfloat16 hh = __float2bfloat16(v);
    h[off] = hh;
    l[off] = __float2bfloat16(v - __bfloat162float(hh));
}

// ---------------------------------------------------------------------------
// HMMA split-bf16 GEMM (R8 proven, unchanged).
// ---------------------------------------------------------------------------
#define GS       144
#define OFF_AL   9216
#define OFF_BH   18432
#define OFF_BL   27648
#define BUFSZ    36864
#define HG_SMEM  (2 * BUFSZ)

__device__ __forceinline__ void mma_bf16(float* c, const uint32_t* a,
                                         const uint32_t* b) {
    asm volatile(
        "mma.sync.aligned.m16n8k16.row.col.f32.bf16.bf16.f32 "
        "{%0,%1,%2,%3}, {%4,%5,%6,%7}, {%8,%9}, {%0,%1,%2,%3};"
        : "+f"(c[0]), "+f"(c[1]), "+f"(c[2]), "+f"(c[3])
        : "r"(a[0]), "r"(a[1]), "r"(a[2]), "r"(a[3]), "r"(b[0]), "r"(b[1]));
}
__device__ __forceinline__ void cp16(uint32_t s, const void* g) {
    asm volatile("cp.async.cg.shared.global [%0], [%1], 16;" :: "r"(s), "l"(g));
}
__device__ __forceinline__ uint32_t lds32(uint32_t a) {
    uint32_t v; asm("ld.shared.b32 %0,[%1];" : "=r"(v) : "r"(a)); return v;
}

__global__ __launch_bounds__(128)
void hmma_gemm(const __nv_bfloat16* __restrict__ Ah, const __nv_bfloat16* __restrict__ Al,
               const __nv_bfloat16* __restrict__ Bh, const __nv_bfloat16* __restrict__ Bl,
               const float* __restrict__ bias, float* __restrict__ C, int Ncols)
{
    extern __shared__ char smem[];
    const uint32_t sb = smem_u32(smem);
    const int tid = threadIdx.x;
    const int w = tid >> 5, lane = tid & 31;
    const int g = lane >> 2, tg = lane & 3;
    const int m0 = blockIdx.y * 64, n0 = blockIdx.x * 64;
    const int wm = (w >> 1) * 32, wn = (w & 1) * 32;

    float acc[2][4][4];
    #pragma unroll
    for (int mt = 0; mt < 2; mt++)
        #pragma unroll
        for (int nt = 0; nt < 4; nt++)
            #pragma unroll
            for (int i = 0; i < 4; i++) acc[mt][nt][i] = 0.f;

    #define ISSUE_CHUNK(cc, pp) do {                                          \
        int k0_ = (cc) * 64;                                                  \
        uint32_t dst_ = sb + (pp) * BUFSZ;                                    \
        _Pragma("unroll")                                                     \
        for (int v_ = 0; v_ < 4; v_++) {                                      \
            int f_ = v_ * 128 + tid;                                          \
            int row_ = f_ >> 3, cg_ = f_ & 7;                                 \
            uint32_t so_ = row_ * GS + cg_ * 16;                              \
            size_t ga_ = (size_t)(m0 + row_) * CDIM + k0_ + cg_ * 8;          \
            size_t gb_ = (size_t)(n0 + row_) * CDIM + k0_ + cg_ * 8;          \
            cp16(dst_ + so_,          Ah + ga_);                              \
            cp16(dst_ + OFF_AL + so_, Al + ga_);                              \
            cp16(dst_ + OFF_BH + so_, Bh + gb_);                              \
            cp16(dst_ + OFF_BL + so_, Bl + gb_);                              \
        }                                                                     \
        asm volatile("cp.async.commit_group;");                               \
    } while (0)

    ISSUE_CHUNK(0, 0);
    ISSUE_CHUNK(1, 1);

    for (int c = 0; c < 8; ++c) {
        if (c == 7) asm volatile("cp.async.wait_group 0;" ::: "memory");
        else        asm volatile("cp.async.wait_group 1;" ::: "memory");
        __syncthreads();

        const uint32_t buf = sb + (c & 1) * BUFSZ;
        #pragma unroll
        for (int ks = 0; ks < 4; ks++) {
            uint32_t aH[2][4], aL[2][4], bH[4][2], bL[4][2];
            #pragma unroll
            for (int mt = 0; mt < 2; mt++) {
                uint32_t ad = buf + (wm + mt * 16 + g) * GS + ks * 32 + tg * 4;
                aH[mt][0] = lds32(ad);
                aH[mt][1] = lds32(ad + 8 * GS);
                aH[mt][2] = lds32(ad + 16);
                aH[mt][3] = lds32(ad + 8 * GS + 16);
                uint32_t al = ad + OFF_AL;
                aL[mt][0] = lds32(al);
                aL[mt][1] = lds32(al + 8 * GS);
                aL[mt][2] = lds32(al + 16);
                aL[mt][3] = lds32(al + 8 * GS + 16);
            }
            #pragma unroll
            for (int nt = 0; nt < 4; nt++) {
                uint32_t bd = buf + OFF_BH + (wn + nt * 8 + g) * GS + ks * 32 + tg * 4;
                bH[nt][0] = lds32(bd);
                bH[nt][1] = lds32(bd + 16);
                uint32_t bl = bd + (OFF_BL - OFF_BH);
                bL[nt][0] = lds32(bl);
                bL[nt][1] = lds32(bl + 16);
            }
            #pragma unroll
            for (int mt = 0; mt < 2; mt++)
                #pragma unroll
                for (int nt = 0; nt < 4; nt++) {
                    mma_bf16(acc[mt][nt], aH[mt], bH[nt]);
                    mma_bf16(acc[mt][nt], aH[mt], bL[nt]);
                    mma_bf16(acc[mt][nt], aL[mt], bH[nt]);
                }
        }
        __syncthreads();
        if (c + 2 < 8) ISSUE_CHUNK(c + 2, c & 1);
    }

    #pragma unroll
    for (int mt = 0; mt < 2; mt++) {
        int r0 = m0 + wm + mt * 16 + g;
        #pragma unroll
        for (int nt = 0; nt < 4; nt++) {
            int col = n0 + wn + nt * 8 + tg * 2;
            float b0 = 0.f, b1 = 0.f;
            if (bias) { b0 = bias[col]; b1 = bias[col + 1]; }
            *(float2*)&C[(size_t)r0 * Ncols + col] =
                make_float2(acc[mt][nt][0] + b0, acc[mt][nt][1] + b1);
            *(float2*)&C[(size_t)(r0 + 8) * Ncols + col] =
                make_float2(acc[mt][nt][2] + b0, acc[mt][nt][3] + b1);
        }
    }
    #undef ISSUE_CHUNK
}

// ---------------------------------------------------------------------------
// Trig precompute (unchanged).
// ---------------------------------------------------------------------------
__global__ __launch_bounds__(256)
void trig_prep(const float* __restrict__ qkv, const float* __restrict__ paramR,
               float* __restrict__ gqs, float* __restrict__ gqc,
               float* __restrict__ gknv, float* __restrict__ gkns,
               float* __restrict__ gkc)
{
    int i = blockIdx.x * 256 + threadIdx.x;
    const float R = paramR[0];
    int tok = i >> 9, col = i & 511;
    float qv = qkv[tok * QKVD + col];
    float s, c;
    sincosf(R * qv, &s, &c);
    gqs[i] = s; gqc[i] = c;
    float kv = qkv[tok * QKVD + CDIM + col];
    sincosf(R * kv, &s, &c);
    gknv[i] = -kv; gkns[i] = -s; gkc[i] = c;
}

// ---------------------------------------------------------------------------
// Fused Fourier attention. d4-granular LDS.128 score loop (R5-proven layout),
// online PV, epilogue writes bf16 hi/lo directly for the proj GEMM.
// ---------------------------------------------------------------------------
#define KREG 17408
static const int ATTN_SMEM = (3 * 16 * CH + KREG + 8 * QT + QT) * 4;

__global__ __launch_bounds__(256, 2)
void fourier_attn4(const float* __restrict__ qkv,
                   const float* __restrict__ gqs, const float* __restrict__ gqc,
                   const float* __restrict__ gknv, const float* __restrict__ gkns,
                   const float* __restrict__ gkc,
                   const float* __restrict__ paramR,
                   __nv_bfloat16* __restrict__ outh,
                   __nv_bfloat16* __restrict__ outl)
{
    extern __shared__ float sm[];
    float* sQv = sm;                      // [16][CH]
    float* sQs = sQv + 16 * CH;
    float* sQc = sQs + 16 * CH;
    float* smK = sQc + 16 * CH;
    float* sKv = smK;                     // [64][64]
    float* sKs = smK + 4096;
    float* sKc = smK + 8192;
    float* sV  = smK + 12288;
    float* sRed = smK + KREG;

    const int tid = threadIdx.x;
    const int q = tid & 31, kg = tid >> 5;
    const int qt = blockIdx.x, h = blockIdx.y, b = blockIdx.z;
    const int tok0 = b * NSEQ, q0 = qt * QT;
    const float R = paramR[0];

    // q-side fill: chunked [d4][q][4]
    for (int i = tid; i < QT * 16; i += 256) {
        int d4 = i & 15, qq = i >> 4;
        int g = (tok0 + q0 + qq) * CDIM + h * DH + d4 * 4;
        int sidx = d4 * CH + qq * 4;
        *(float4*)&sQs[sidx] = *(const float4*)&gqs[g];
        *(float4*)&sQc[sidx] = *(const float4*)&gqc[g];
        *(float4*)&sQv[sidx] = *(const float4*)&qkv[(tok0 + q0 + qq) * QKVD + h * DH + d4 * 4];
    }

    u64 acc[32];
    #pragma unroll
    for (int i = 0; i < 32; i++) acc[i] = 0ull;
    float rowsum = 0.f;

    for (int kc0 = 0; kc0 < NSEQ; kc0 += KT) {
        __syncthreads();
        for (int i = tid; i < KT * 16; i += 256) {
            int kk = i >> 4, dq = (i & 15) * 4;
            int g = (tok0 + kc0 + kk) * CDIM + h * DH + dq;
            int sidx = kk * DH + dq;
            *(float4*)&sKv[sidx] = *(const float4*)&gknv[g];
            *(float4*)&sKs[sidx] = *(const float4*)&gkns[g];
            *(float4*)&sKc[sidx] = *(const float4*)&gkc[g];
            *(float4*)&sV[sidx]  = *(const float4*)&qkv[(tok0 + kc0 + kk) * QKVD + 2 * CDIM + h * DH + dq];
        }
        __syncthreads();

        float np[8], dp[8];
        #pragma unroll
        for (int j = 0; j < 8; j++) { np[j] = 1.f; dp[j] = 1.f; }
        const int kb0 = kg * 8 * DH;

        #pragma unroll 2
        for (int d4 = 0; d4 < 16; d4++) {
            int qidx = d4 * CH + q * 4;
            ulonglong2 qv = *(const ulonglong2*)&sQv[qidx];
            ulonglong2 qs = *(const ulonglong2*)&sQs[qidx];
            ulonglong2 qc = *(const ulonglong2*)&sQc[qidx];
            #pragma unroll
            for (int j = 0; j < 8; j++) {
                int koff = kb0 + j * DH + d4 * 4;
                ulonglong2 kv = *(const ulonglong2*)&sKv[koff];
                ulonglong2 ks = *(const ulonglong2*)&sKs[koff];
                ulonglong2 kc = *(const ulonglong2*)&sKc[koff];
                u64 dfa = fadd2(qv.x, kv.x);                    // q-k, dims 0,1
                u64 dfb = fadd2(qv.y, kv.y);                    // dims 2,3
                u64 nma = ffma2(qs.x, kc.x, fmul2(qc.x, ks.x)); // sin(R(q-k))
                u64 nmb = ffma2(qs.y, kc.y, fmul2(qc.y, ks.y));
                float d0, d1, d2, d3, n0, n1, n2, n3;
                up2(dfa, d0, d1); up2(dfb, d2, d3);
                up2(nma, n0, n1); up2(nmb, n2, n3);
                bool s0 = fabsf(d0) < T_SMALL, s1 = fabsf(d1) < T_SMALL;
                bool s2 = fabsf(d2) < T_SMALL, s3 = fabsf(d3) < T_SMALL;
                np[j] *= s0 ? R : n0;  dp[j] *= s0 ? 1.f : d0;
                np[j] *= s1 ? R : n1;  dp[j] *= s1 ? 1.f : d1;
                np[j] *= s2 ? R : n2;  dp[j] *= s2 ? 1.f : d2;
                np[j] *= s3 ? R : n3;  dp[j] *= s3 ? 1.f : d3;
            }
        }

        // a4 + online PV over this thread's 8 keys, all 64 dims
        #pragma unroll
        for (int j = 0; j < 8; j++) {
            float s = (dp[j] != 0.f) ? np[j] / dp[j] : 0.f;
            float s2 = s * s;
            float a4 = s2 * s2;
            rowsum += a4;
            u64 aa = pk2(a4, a4);
            const ulonglong2* vp = (const ulonglong2*)&sV[(kg * 8 + j) * DH];
            #pragma unroll
            for (int w = 0; w < 16; w++) {
                ulonglong2 vv = vp[w];
                acc[2 * w]     = ffma2(aa, vv.x, acc[2 * w]);
                acc[2 * w + 1] = ffma2(aa, vv.y, acc[2 * w + 1]);
            }
        }
    }
    __syncthreads();

    sRed[kg * 32 + q] = rowsum;
    {
        float* myAcc = &smK[(kg * 32 + q) * 68];
        #pragma unroll
        for (int w = 0; w < 16; w++) {
            ulonglong2 vv; vv.x = acc[2 * w]; vv.y = acc[2 * w + 1];
            *(ulonglong2*)&myAcc[w * 4] = vv;
        }
    }
    __syncthreads();

    float ss = 0.f;
    #pragma unroll
    for (int r = 0; r < 8; r++) ss += sRed[r * 32 + q];
    float inv = 1.f / (ss + EPSF);
    u64 inv2 = pk2(inv, inv);

    u64 o[4];
    #pragma unroll
    for (int i = 0; i < 4; i++) o[i] = 0ull;
    #pragma unroll
    for (int kgp = 0; kgp < 8; kgp++) {
        const float* src = &smK[(kgp * 32 + q) * 68 + kg * 8];
        ulonglong2 v0 = *(const ulonglong2*)src;
        ulonglong2 v1 = *(const ulonglong2*)(src + 4);
        o[0] = fadd2(o[0], v0.x); o[1] = fadd2(o[1], v0.y);
        o[2] = fadd2(o[2], v1.x); o[3] = fadd2(o[3], v1.y);
    }
    #pragma unroll
    for (int i = 0; i < 4; i++) o[i] = fmul2(o[i], inv2);

    float of[8];
    up2(o[0], of[0], of[1]); up2(o[1], of[2], of[3]);
    up2(o[2], of[4], of[5]); up2(o[3], of[6], of[7]);

    // split to bf16 hi/lo directly (feeds proj HMMA)
    __nv_bfloat16 hb[8], lb[8];
    #pragma unroll
    for (int i = 0; i < 8; i++) {
        __nv_bfloat16 hh = __float2bfloat16(of[i]);
        hb[i] = hh;
        lb[i] = __float2bfloat16(of[i] - __bfloat162float(hh));
    }
    size_t base = (size_t)(tok0 + q0 + q) * CDIM + h * DH + kg * 8;
    *(uint4*)&outh[base] = *(const uint4*)hb;
    *(uint4*)&outl[base] = *(const uint4*)lb;
}

extern "C" void kernel_launch(void* const* d_in, const int* in_sizes, int n_in,
                              void* d_out, int out_size)
{
    const float* x      = (const float*)d_in[0];
    const float* w_qkv  = (const float*)d_in[1];
    const float* w_proj = (const float*)d_in[2];
    const float* b_proj = (const float*)d_in[3];
    const float* paramR = (const float*)d_in[4];
    float* out = (float*)d_out;

    float *qkvbuf, *gqs, *gqc, *gknv, *gkns, *gkc;
    __nv_bfloat16 *xh, *xl, *wqh, *wql, *wph, *wpl, *ath, *atl;
    cudaGetSymbolAddress((void**)&qkvbuf, g_qkv);
    cudaGetSymbolAddress((void**)&gqs,  g_qs);
    cudaGetSymbolAddress((void**)&gqc,  g_qc);
    cudaGetSymbolAddress((void**)&gknv, g_knv);
    cudaGetSymbolAddress((void**)&gkns, g_kns);
    cudaGetSymbolAddress((void**)&gkc,  g_kc);
    cudaGetSymbolAddress((void**)&xh,  g_xh);
    cudaGetSymbolAddress((void**)&xl,  g_xl);
    cudaGetSymbolAddress((void**)&wqh, g_wqh);
    cudaGetSymbolAddress((void**)&wql, g_wql);
    cudaGetSymbolAddress((void**)&wph, g_wph);
    cudaGetSymbolAddress((void**)&wpl, g_wpl);
    cudaGetSymbolAddress((void**)&ath, g_ath);
    cudaGetSymbolAddress((void**)&atl, g_atl);

    cudaFuncSetAttribute(fourier_attn4, cudaFuncAttributeMaxDynamicSharedMemorySize,
                         ATTN_SMEM);
    cudaFuncSetAttribute(hmma_gemm, cudaFuncAttributeMaxDynamicSharedMemorySize,
                         HG_SMEM);

    // 0) one merged split of all fp32 inputs to bf16 hi/lo
    split_all<<<(NX + NQ + NP) / 256, 256>>>(x, w_qkv, w_proj,
                                             xh, xl, wqh, wql, wph, wpl);

    // 1) qkv = x @ w_qkv^T via HMMA (384 CTAs)
    hmma_gemm<<<dim3(QKVD / 64, TOKENS / 64), 128, HG_SMEM>>>(
        xh, xl, wqh, wql, nullptr, qkvbuf, QKVD);

    // 2) trig precompute
    trig_prep<<<TOKENS * CDIM / 256, 256>>>(qkvbuf, paramR, gqs, gqc, gknv, gkns, gkc);

    // 3) fused attention, writes bf16 hi/lo directly
    fourier_attn4<<<dim3(NSEQ / QT, HEADS, 4), 256, ATTN_SMEM>>>(
        qkvbuf, gqs, gqc, gknv, gkns, gkc, paramR, ath, atl);

    // 4) proj via HMMA (128 CTAs)
    hmma_gemm<<<dim3(CDIM / 64, TOKENS / 64), 128, HG_SMEM>>>(
        ath, atl, wph, wpl, b_proj, out, CDIM);
}